// round 8
// baseline (speedup 1.0000x reference)
#include <cuda_runtime.h>
#include <cuda_bf16.h>

// Sparsemax over rows: x, mask are [8192, 4096] fp32; out fp32 same shape.
// z = (mask ? x : NEG_BIG) * 2 ; tau solves sum(relu(z - tau)) = 1 (Newton);
// out = relu(z - tau)  (mask multiply implied: masked z is hugely negative).
//
// R8 = R7 (front-batched loads, double-buffered single-barrier Newton,
// __fdividef, 5 CTAs/SM) + REDUX.SUM (__reduce_add_sync) for the support
// count, replacing its 5-shuffle chain with one instruction that overlaps
// the float-sum shuffle chain.

#define ROWS 8192
#define COLS 4096
#define THREADS 256
#define NWARPS (THREADS / 32)
#define ELEMS (COLS / THREADS)   // 16 floats per thread
#define VEC (ELEMS / 4)          // 4 float4 per thread

__global__ __launch_bounds__(THREADS, 5)
void sparsemax_kernel(const float* __restrict__ x,
                      const float* __restrict__ m,
                      float* __restrict__ out) {
    const int row = blockIdx.x;
    const int t   = threadIdx.x;
    const int lane = t & 31;
    const int wid  = t >> 5;

    const float4* __restrict__ xr = reinterpret_cast<const float4*>(x + (size_t)row * COLS);
    const float4* __restrict__ mr = reinterpret_cast<const float4*>(m + (size_t)row * COLS);
    float4* __restrict__ orow     = reinterpret_cast<float4*>(out + (size_t)row * COLS);

    // Double-buffered reduction scratch: buffer b holds (s[8] float, c[8] int).
    __shared__ float shs[2][NWARPS];
    __shared__ int   shc[2][NWARPS];

    // ---- Front-batch ALL loads (8 x LDG.128 in flight per thread) ----
    float4 xv[VEC];
    float4 mv[VEC];
#pragma unroll
    for (int v = 0; v < VEC; v++) xv[v] = xr[t + v * THREADS];
#pragma unroll
    for (int v = 0; v < VEC; v++) mv[v] = mr[t + v * THREADS];

    // ---- Apply mask + temperature, track local max ----
    float z[ELEMS];
    float vmax = -3.0e38f;
    const float NEGZ = -9999999.9f * 2.0f;  // masked value after temperature
#pragma unroll
    for (int v = 0; v < VEC; v++) {
        float z0 = (mv[v].x != 0.0f) ? (xv[v].x * 2.0f) : NEGZ;
        float z1 = (mv[v].y != 0.0f) ? (xv[v].y * 2.0f) : NEGZ;
        float z2 = (mv[v].z != 0.0f) ? (xv[v].z * 2.0f) : NEGZ;
        float z3 = (mv[v].w != 0.0f) ? (xv[v].w * 2.0f) : NEGZ;
        z[v * 4 + 0] = z0;
        z[v * 4 + 1] = z1;
        z[v * 4 + 2] = z2;
        z[v * 4 + 3] = z3;
        vmax = fmaxf(vmax, fmaxf(fmaxf(z0, z1), fmaxf(z2, z3)));
    }

    // ---- Block max reduction (buffer 0 of shs; iteration 0 then writes
    //      buffer 1, so no trailing barrier is needed). ----
#pragma unroll
    for (int o = 16; o > 0; o >>= 1)
        vmax = fmaxf(vmax, __shfl_xor_sync(0xFFFFFFFFu, vmax, o));
    if (lane == 0) shs[0][wid] = vmax;
    __syncthreads();
    float zmax = -3.0e38f;
#pragma unroll
    for (int i = 0; i < NWARPS; i++) zmax = fmaxf(zmax, shs[0][i]);

    // ---- Newton on f(T) = sum(relu(z - T)) - 1, from the left ----
    // T0 = zmax - 1 guarantees f(T0) >= 0; Newton from the left is monotone
    // increasing on convex piecewise-linear f and terminates exactly.
    float T = zmax - 1.0f;
#pragma unroll 1
    for (int it = 0; it < 32; ++it) {
        const int b = (it & 1) ^ 1;   // iter 0 -> buffer 1, iter 1 -> buffer 0, ...
        float s = 0.0f;
        int   c = 0;
#pragma unroll
        for (int e = 0; e < ELEMS; e++) {
            float d = z[e] - T;
            if (d > 0.0f) { s += d; c += 1; }
        }
        // Count: single REDUX.SUM; overlaps the float shuffle chain below.
        c = (int)__reduce_add_sync(0xFFFFFFFFu, (unsigned)c);
#pragma unroll
        for (int o = 16; o > 0; o >>= 1)
            s += __shfl_xor_sync(0xFFFFFFFFu, s, o);
        if (lane == 0) { shs[b][wid] = s; shc[b][wid] = c; }
        __syncthreads();   // buffer b visible; buffer b^1 now free
        float S = 0.0f;
        int   C = 0;
#pragma unroll
        for (int i = 0; i < NWARPS; i++) { S += shs[b][i]; C += shc[b][i]; }

        if (C == 0) break;                // degenerate guard (shouldn't happen)
        float delta = __fdividef(S - 1.0f, (float)C);  // MUFU.RCP fast path
        T += delta;
        if (fabsf(delta) < 1e-6f) break;  // uniform across block (S,C identical)
    }

    // ---- Output: relu(z - T). Masked entries are ~-2e7, relu -> 0. ----
#pragma unroll
    for (int v = 0; v < VEC; v++) {
        float4 ov;
        ov.x = fmaxf(0.0f, z[v * 4 + 0] - T);
        ov.y = fmaxf(0.0f, z[v * 4 + 1] - T);
        ov.z = fmaxf(0.0f, z[v * 4 + 2] - T);
        ov.w = fmaxf(0.0f, z[v * 4 + 3] - T);
        orow[t + v * THREADS] = ov;
    }
}

extern "C" void kernel_launch(void* const* d_in, const int* in_sizes, int n_in,
                              void* d_out, int out_size) {
    const float* x = (const float*)d_in[0];
    const float* m = (const float*)d_in[1];
    float* out = (float*)d_out;
    sparsemax_kernel<<<ROWS, THREADS>>>(x, m, out);
}

// round 9
// speedup vs baseline: 1.0179x; 1.0179x over previous
#include <cuda_runtime.h>
#include <cuda_bf16.h>

// Sparsemax over rows: x, mask are [8192, 4096] fp32; out fp32 same shape.
// z = (mask ? x : NEG_BIG) * 2 ; tau solves sum(relu(z - tau)) = 1 ;
// out = relu(z - tau)  (mask multiply implied: masked z is hugely negative).
//
// R9: tau >= zmax - 1, so the support set lies in {z > zmax - 1} (typically
// 2-6 elements). Gather those candidates to shared with a deterministic
// prefix-scan (2 barriers), then EVERY warp redundantly runs a warp-local
// Newton on the tiny list (shuffles only, no barriers). Fallback to the
// proven block-Newton if the candidate set overflows (never for this data).

#define ROWS 8192
#define COLS 4096
#define THREADS 256
#define NWARPS (THREADS / 32)
#define ELEMS (COLS / THREADS)   // 16 floats per thread
#define VEC (ELEMS / 4)          // 4 float4 per thread
#define CAP 128                  // candidate buffer (4 per lane)

__global__ __launch_bounds__(THREADS, 5)
void sparsemax_kernel(const float* __restrict__ x,
                      const float* __restrict__ m,
                      float* __restrict__ out) {
    const int row = blockIdx.x;
    const int t   = threadIdx.x;
    const int lane = t & 31;
    const int wid  = t >> 5;

    const float4* __restrict__ xr = reinterpret_cast<const float4*>(x + (size_t)row * COLS);
    const float4* __restrict__ mr = reinterpret_cast<const float4*>(m + (size_t)row * COLS);
    float4* __restrict__ orow     = reinterpret_cast<float4*>(out + (size_t)row * COLS);

    __shared__ float shs[2][NWARPS];   // reduce scratch (max / fallback s)
    __shared__ int   shc[2][NWARPS];   // warp candidate counts / fallback c
    __shared__ float cand[CAP];        // gathered candidates

    // ---- Front-batch ALL loads (8 x LDG.128 in flight per thread) ----
    float4 xv[VEC];
    float4 mv[VEC];
#pragma unroll
    for (int v = 0; v < VEC; v++) xv[v] = xr[t + v * THREADS];
#pragma unroll
    for (int v = 0; v < VEC; v++) mv[v] = mr[t + v * THREADS];

    // ---- Apply mask + temperature, track local max ----
    float z[ELEMS];
    float vmax = -3.0e38f;
    const float NEGZ = -9999999.9f * 2.0f;  // masked value after temperature
#pragma unroll
    for (int v = 0; v < VEC; v++) {
        float z0 = (mv[v].x != 0.0f) ? (xv[v].x * 2.0f) : NEGZ;
        float z1 = (mv[v].y != 0.0f) ? (xv[v].y * 2.0f) : NEGZ;
        float z2 = (mv[v].z != 0.0f) ? (xv[v].z * 2.0f) : NEGZ;
        float z3 = (mv[v].w != 0.0f) ? (xv[v].w * 2.0f) : NEGZ;
        z[v * 4 + 0] = z0;
        z[v * 4 + 1] = z1;
        z[v * 4 + 2] = z2;
        z[v * 4 + 3] = z3;
        vmax = fmaxf(vmax, fmaxf(fmaxf(z0, z1), fmaxf(z2, z3)));
    }

    // ---- Block max reduction ----
#pragma unroll
    for (int o = 16; o > 0; o >>= 1)
        vmax = fmaxf(vmax, __shfl_xor_sync(0xFFFFFFFFu, vmax, o));
    if (lane == 0) shs[0][wid] = vmax;
    __syncthreads();                       // barrier 1
    float zmax = -3.0e38f;
#pragma unroll
    for (int i = 0; i < NWARPS; i++) zmax = fmaxf(zmax, shs[0][i]);

    const float T0 = zmax - 1.0f;

    // ---- Count candidates (z > T0) per thread; deterministic warp scan ----
    int lc = 0;
#pragma unroll
    for (int e = 0; e < ELEMS; e++) lc += (z[e] > T0) ? 1 : 0;

    int inc = lc;                          // inclusive prefix over lanes
#pragma unroll
    for (int o = 1; o < 32; o <<= 1) {
        int v = __shfl_up_sync(0xFFFFFFFFu, inc, o);
        if (lane >= o) inc += v;
    }
    const int excl = inc - lc;
    const int wtot = __shfl_sync(0xFFFFFFFFu, inc, 31);
    if (lane == 31) shc[1][wid] = wtot;
    __syncthreads();                       // barrier 2

    int base = 0, n = 0;
#pragma unroll
    for (int i = 0; i < NWARPS; i++) {
        int w = shc[1][i];
        if (i < wid) base += w;
        n += w;
    }

    float tau;
    if (n <= CAP) {
        // ---- Write candidates at deterministic slots ----
        int off = base + excl;
#pragma unroll
        for (int e = 0; e < ELEMS; e++) {
            if (z[e] > T0) cand[off++] = z[e];
        }
        __syncthreads();                   // barrier 3 (last barrier)

        // ---- Warp-local Newton (every warp redundantly; identical tau) ----
        float c0 = (lane +  0 < n) ? cand[lane +  0] : -3.0e38f;
        float c1 = (lane + 32 < n) ? cand[lane + 32] : -3.0e38f;
        float c2 = (lane + 64 < n) ? cand[lane + 64] : -3.0e38f;
        float c3 = (lane + 96 < n) ? cand[lane + 96] : -3.0e38f;

        float T = T0;
#pragma unroll 1
        for (int it = 0; it < 32; ++it) {
            float s = 0.0f, c = 0.0f;
            float d;
            d = c0 - T; if (d > 0.0f) { s += d; c += 1.0f; }
            d = c1 - T; if (d > 0.0f) { s += d; c += 1.0f; }
            d = c2 - T; if (d > 0.0f) { s += d; c += 1.0f; }
            d = c3 - T; if (d > 0.0f) { s += d; c += 1.0f; }
#pragma unroll
            for (int o = 16; o > 0; o >>= 1) {
                s += __shfl_xor_sync(0xFFFFFFFFu, s, o);
                c += __shfl_xor_sync(0xFFFFFFFFu, c, o);
            }
            if (c < 0.5f) break;           // degenerate (all-masked row)
            float delta = __fdividef(s - 1.0f, c);
            T += delta;
            if (fabsf(delta) < 1e-6f) break;
        }
        tau = T;
    } else {
        // ---- Fallback: proven block-Newton (block-uniform branch) ----
        __syncthreads();
        float T = T0;
#pragma unroll 1
        for (int it = 0; it < 32; ++it) {
            const int b = (it & 1) ^ 1;
            float s = 0.0f;
            int   c = 0;
#pragma unroll
            for (int e = 0; e < ELEMS; e++) {
                float d = z[e] - T;
                if (d > 0.0f) { s += d; c += 1; }
            }
#pragma unroll
            for (int o = 16; o > 0; o >>= 1) {
                s += __shfl_xor_sync(0xFFFFFFFFu, s, o);
                c += __shfl_xor_sync(0xFFFFFFFFu, c, o);
            }
            if (lane == 0) { shs[b][wid] = s; shc[b][wid] = c; }
            __syncthreads();
            float S = 0.0f;
            int   C = 0;
#pragma unroll
            for (int i = 0; i < NWARPS; i++) { S += shs[b][i]; C += shc[b][i]; }

            if (C == 0) break;
            float delta = __fdividef(S - 1.0f, (float)C);
            T += delta;
            if (fabsf(delta) < 1e-6f) break;
        }
        tau = T;
    }

    // ---- Output: relu(z - tau). Masked entries are ~-2e7, relu -> 0. ----
#pragma unroll
    for (int v = 0; v < VEC; v++) {
        float4 ov;
        ov.x = fmaxf(0.0f, z[v * 4 + 0] - tau);
        ov.y = fmaxf(0.0f, z[v * 4 + 1] - tau);
        ov.z = fmaxf(0.0f, z[v * 4 + 2] - tau);
        ov.w = fmaxf(0.0f, z[v * 4 + 3] - tau);
        orow[t + v * THREADS] = ov;
    }
}

extern "C" void kernel_launch(void* const* d_in, const int* in_sizes, int n_in,
                              void* d_out, int out_size) {
    const float* x = (const float*)d_in[0];
    const float* m = (const float*)d_in[1];
    float* out = (float*)d_out;
    sparsemax_kernel<<<ROWS, THREADS>>>(x, m, out);
}